// round 14
// baseline (speedup 1.0000x reference)
#include <cuda_runtime.h>
#include <cuda_bf16.h>
#include <math.h>

// GAT layer, B=8, N=2048, F=64, ALPHA=0.2
// exp(lrelu(s+d)) = (d > -s) ? exp(s)*exp(d) : exp(.2s)*exp(.2d)
// => sort by d; fused segment-sum + prefix + apply kernel with one
//    grid-wide barrier; per-node denominators precomputed in k2.

#define NB 8
#define NN 2048
#define NF 64
#define NNODES (NB*NN)          // 16384
#define NR1 (NN+1)              // 2049
#define SEGS 64                 // segments per batch
#define SROWS 32                // rows per segment
#define NBLK3 (NB*SEGS)         // 512

// ---- device scratch (no allocation allowed) ----
__device__ float  g_Wh  [NNODES*NF];   // Wh rows, original order
__device__ float  g_s   [NNODES];      // s_src
__device__ float2 g_F12 [NNODES];      // {exp(s), exp(.2s)}
__device__ float  g_d   [NNODES];      // s_dst
__device__ float2 g_E12 [NNODES];      // {exp(d), exp(.2d)} original order
__device__ float2 g_E12s[NNODES];      // sorted order
__device__ int    g_perm[NNODES];      // sorted-rank -> local node idx
__device__ float2 g_R12 [NNODES];      // {f1/denom, f2/denom} per node
__device__ float2 g_seg12[NB*SEGS*NF]; // per-segment sums of E*Wh
__device__ int    g_bucket[NNODES];    // packed (k<<11)|node_local
__device__ int    g_bstart[NB*(SEGS+1)];
__device__ volatile int g_cnt;         // grid barrier counter (reset in k2)

// ============================================================
// K1: Wh = h@W ; s_src/s_dst + exps. 32 nodes/block, grid 512,
// 256 threads (2 nodes x 4 outputs per thread).
// ============================================================
__global__ void __launch_bounds__(256) k1_gemm(
    const float* __restrict__ h, const float* __restrict__ W,
    const float* __restrict__ a)
{
    __shared__ float sW[64*64];
    __shared__ float sh[32][65];
    __shared__ float sa[128];
    int tid = threadIdx.x;
    #pragma unroll
    for (int i = tid; i < 4096; i += 256) sW[i] = W[i];
    if (tid < 128) sa[tid] = a[tid];

    int base = blockIdx.x * 32;
    #pragma unroll
    for (int i = tid; i < 512; i += 256) {      // 32 rows x 16 float4
        int row = i >> 4, c4 = i & 15;
        float4 v = *(const float4*)(h + (base + row)*64 + c4*4);
        sh[row][c4*4+0] = v.x; sh[row][c4*4+1] = v.y;
        sh[row][c4*4+2] = v.z; sh[row][c4*4+3] = v.w;
    }
    __syncthreads();

    int l = tid & 15, grp = tid >> 4;           // 16 lanes x 16 groups
    int o = l * 4;
    int nb = grp * 2;
    float acc[2][4] = {};
    #pragma unroll 8
    for (int f = 0; f < 64; f++) {
        float4 w4 = *(const float4*)(&sW[f*64 + o]);
        #pragma unroll
        for (int e = 0; e < 2; e++) {
            float hf = sh[nb + e][f];
            acc[e][0] += hf*w4.x; acc[e][1] += hf*w4.y;
            acc[e][2] += hf*w4.z; acc[e][3] += hf*w4.w;
        }
    }

    #pragma unroll
    for (int e = 0; e < 2; e++) {
        int node = base + nb + e;
        float4 ov; ov.x=acc[e][0]; ov.y=acc[e][1]; ov.z=acc[e][2]; ov.w=acc[e][3];
        *(float4*)(&g_Wh[node*64 + o]) = ov;
        float ps = acc[e][0]*sa[o]    + acc[e][1]*sa[o+1]
                 + acc[e][2]*sa[o+2]  + acc[e][3]*sa[o+3];
        float pd = acc[e][0]*sa[64+o] + acc[e][1]*sa[64+o+1]
                 + acc[e][2]*sa[64+o+2]+ acc[e][3]*sa[64+o+3];
        #pragma unroll
        for (int m = 8; m >= 1; m >>= 1) {
            ps += __shfl_xor_sync(0xffffffffu, ps, m);
            pd += __shfl_xor_sync(0xffffffffu, pd, m);
        }
        if (l == 0) {
            g_s[node] = ps;
            g_F12[node] = make_float2(expf(ps), expf(0.2f*ps));
            g_d[node] = pd;
            g_E12[node] = make_float2(expf(pd), expf(0.2f*pd));
        }
    }
}

// ============================================================
// K2: per-batch hybrid bitonic sort (smem for j>=32, register
// shuffles for j<=16) + rank search + scalar scans (smem) +
// bucketing + per-node R12. block 1024, grid 8.
// ============================================================
__device__ __forceinline__ unsigned int f2key(float f) {
    unsigned int b = __float_as_uint(f);
    unsigned int m = (unsigned int)(-(int)(b >> 31)) | 0x80000000u;
    return b ^ m;
}

// compare-exchange with partner at stride j (j>=2, intra-warp)
__device__ __forceinline__ unsigned long long ce_shfl(
    unsigned long long e, int i, int j, int k)
{
    unsigned long long pv = __shfl_xor_sync(0xffffffffu, e, j >> 1);
    bool takeMin = (((i & j) == 0) == ((i & k) == 0));
    unsigned long long mn = e < pv ? e : pv;
    unsigned long long mx = e < pv ? pv : e;
    return takeMin ? mn : mx;
}

__device__ __forceinline__ void block_scan_2048(
    const float* sc, float* sout, float* wsum)
{
    int t = threadIdx.x, lane = t & 31, w = t >> 5;
    float x0 = sc[2*t], x1 = sc[2*t+1];
    float v = x0 + x1;
    float s = v;
    #pragma unroll
    for (int d2 = 1; d2 < 32; d2 <<= 1) {
        float nn = __shfl_up_sync(0xffffffffu, s, d2);
        if (lane >= d2) s += nn;
    }
    if (lane == 31) wsum[w] = s;
    __syncthreads();
    if (t < 32) {
        float ws = wsum[t]; float ss = ws;
        #pragma unroll
        for (int d2 = 1; d2 < 32; d2 <<= 1) {
            float nn = __shfl_up_sync(0xffffffffu, ss, d2);
            if (t >= d2) ss += nn;
        }
        wsum[t] = ss - ws;
    }
    __syncthreads();
    float incl = wsum[w] + s;
    float excl = incl - v;
    sout[2*t]   = excl;
    sout[2*t+1] = excl + x0;
    if (t == 1023) sout[2048] = incl;
}

__global__ void __launch_bounds__(1024) k2_sort(void)
{
    __shared__ unsigned long long skv[2048];
    __shared__ float sC1[NR1];
    __shared__ float sC2[NR1];
    __shared__ float wsum[32];
    __shared__ int hist[SEGS];
    __shared__ int hoff[SEGS];
    int b = blockIdx.x, t = threadIdx.x;
    int base = b * NN;
    int i0 = 2*t, i1 = 2*t + 1;

    if (b == 0 && t == 0) g_cnt = 0;   // reset grid barrier for k3
    if (t < SEGS) hist[t] = 0;
    {
        unsigned int ka = f2key(g_d[base + t]);
        unsigned int kb = f2key(g_d[base + t + 1024]);
        skv[t]      = ((unsigned long long)ka << 32) | (unsigned int)t;
        skv[t+1024] = ((unsigned long long)kb << 32) | (unsigned int)(t + 1024);
    }
    __syncthreads();

    // ---- k = 2..32 entirely in registers (thread owns elems 2t, 2t+1)
    {
        unsigned long long e0 = skv[i0], e1 = skv[i1];
        #pragma unroll
        for (int k = 2; k <= 32; k <<= 1) {
            #pragma unroll
            for (int j = k >> 1; j >= 2; j >>= 1) {
                e0 = ce_shfl(e0, i0, j, k);
                e1 = ce_shfl(e1, i1, j, k);
            }
            bool up = (i0 & k) == 0;
            unsigned long long mn = e0 < e1 ? e0 : e1;
            unsigned long long mx = e0 < e1 ? e1 : e0;
            e0 = up ? mn : mx;
            e1 = up ? mx : mn;
        }
        skv[i0] = e0; skv[i1] = e1;
    }
    __syncthreads();

    // ---- k = 64..2048: strides >=32 in smem, <=16 in registers
    for (int k = 64; k <= 2048; k <<= 1) {
        for (int j = k >> 1; j >= 32; j >>= 1) {
            #pragma unroll
            for (int e = 0; e < 2; e++) {
                int i = t + e*1024;
                int ixj = i ^ j;
                if (ixj > i) {
                    bool up2 = ((i & k) == 0);
                    unsigned long long vi = skv[i], vj = skv[ixj];
                    if ((vi > vj) == up2) { skv[i] = vj; skv[ixj] = vi; }
                }
            }
            __syncthreads();
        }
        unsigned long long e0 = skv[i0], e1 = skv[i1];
        #pragma unroll
        for (int j = 16; j >= 2; j >>= 1) {
            e0 = ce_shfl(e0, i0, j, k);
            e1 = ce_shfl(e1, i1, j, k);
        }
        bool up = (i0 & k) == 0;
        unsigned long long mn = e0 < e1 ? e0 : e1;
        unsigned long long mx = e0 < e1 ? e1 : e0;
        skv[i0] = up ? mn : mx;
        skv[i1] = up ? mx : mn;
        __syncthreads();
    }

    // write perm + gathered exps
    int p0 = (int)(unsigned int)skv[t];
    int p1 = (int)(unsigned int)skv[t + 1024];
    g_perm[base + t]        = p0;
    g_perm[base + t + 1024] = p1;
    float2 ea = g_E12[base + p0];
    float2 eb = g_E12[base + p1];
    g_E12s[base + t]        = ea;
    g_E12s[base + t + 1024] = eb;

    // per-node rank search + bucket tally (keys intact in skv)
    int kk[2], sg[2];
    #pragma unroll
    for (int e = 0; e < 2; e++) {
        int n = base + t + e*1024;
        unsigned int thrk = f2key(-g_s[n]);
        int lo = 0, hi = NN;
        while (lo < hi) {
            int mid = (lo + hi) >> 1;
            if ((unsigned int)(skv[mid] >> 32) <= thrk) lo = mid + 1; else hi = mid;
        }
        kk[e] = lo;
        sg[e] = min(lo >> 5, SEGS-1);
        atomicAdd(&hist[sg[e]], 1);
    }
    __syncthreads();

    if (t == 0) {
        int acc = 0;
        #pragma unroll
        for (int s2 = 0; s2 < SEGS; s2++) { hoff[s2] = acc; acc += hist[s2]; }
    }
    __syncthreads();
    if (t < SEGS) g_bstart[b*(SEGS+1) + t] = hoff[t];
    if (t == 0)   g_bstart[b*(SEGS+1) + SEGS] = NN;
    __syncthreads();

    #pragma unroll
    for (int e = 0; e < 2; e++) {
        int nloc = t + e*1024;
        int slot = atomicAdd(&hoff[sg[e]], 1);
        g_bucket[base + slot] = (kk[e] << 11) | nloc;
    }
    __syncthreads();

    // scalar prefix scans into smem (reuse skv as float buffer)
    float* sc = (float*)skv;
    sc[t] = ea.x; sc[t+1024] = eb.x;
    __syncthreads();
    block_scan_2048(sc, sC1, wsum);
    __syncthreads();
    sc[t] = ea.y; sc[t+1024] = eb.y;
    __syncthreads();
    block_scan_2048(sc, sC2, wsum);
    __syncthreads();

    // per-node reciprocal denominators
    float C1tot = sC1[NN];
    #pragma unroll
    for (int e = 0; e < 2; e++) {
        int n = base + t + e*1024;
        int k = kk[e];
        float2 f = g_F12[n];
        float denom = f.x*(C1tot - sC1[k]) + f.y*sC2[k];
        float inv = 1.0f / denom;
        g_R12[n] = make_float2(f.x*inv, f.y*inv);
    }
}

// ============================================================
// K3: fused segment sums + grid barrier + prefixes + apply
// (bucket words + R12 prefetched to smem in chunks).
// grid NBLK3=512, block 256 (o=tid&63, sub=tid>>6).
// ============================================================
__global__ void __launch_bounds__(256, 4) k3_fused(float* __restrict__ out)
{
    int blk = blockIdx.x;
    int b = blk >> 6, seg = blk & 63;
    int t = threadIdx.x;
    int o = t & 63, sub = t >> 6;

    __shared__ int    sperm[SROWS];
    __shared__ float2 sE[SROWS];
    if (t < SROWS) {
        sperm[t] = g_perm[b*NN + seg*SROWS + t];
        sE[t]    = g_E12s[b*NN + seg*SROWS + t];
    }
    __syncthreads();

    // own 8-row partials; cache gathered Wh + E in registers
    float w[8]; float2 e[8];
    float2 loc = make_float2(0.f, 0.f);
    #pragma unroll
    for (int rr = 0; rr < 8; rr++) {
        int lr = sub*8 + rr;
        w[rr] = g_Wh[(b*NN + sperm[lr])*64 + o];
        e[rr] = sE[lr];
        loc.x += e[rr].x * w[rr];
        loc.y += e[rr].y * w[rr];
    }

    __shared__ float2 sloc[4][64];
    sloc[sub][o] = loc;
    __syncthreads();

    // publish this segment's aggregate
    if (sub == 0) {
        float2 agg = make_float2(
            sloc[0][o].x + sloc[1][o].x + sloc[2][o].x + sloc[3][o].x,
            sloc[0][o].y + sloc[1][o].y + sloc[2][o].y + sloc[3][o].y);
        g_seg12[blk*64 + o] = agg;
    }
    __syncthreads();

    // grid-wide barrier: release(writes) -> arrive -> spin
    if (t == 0) {
        __threadfence();
        atomicAdd((int*)&g_cnt, 1);
        while (g_cnt < NBLK3) { }
    }
    __syncthreads();

    // strided pass over all 64 segment sums
    float2 bef = make_float2(0.f, 0.f);
    float2 tot = make_float2(0.f, 0.f);
    for (int s = sub; s < SEGS; s += 4) {
        float2 v = __ldcg(&g_seg12[(b*SEGS + s)*64 + o]);
        tot.x += v.x; tot.y += v.y;
        if (s < seg) { bef.x += v.x; bef.y += v.y; }
    }

    __shared__ float2 sbef[4][64], stot[4][64];
    sbef[sub][o] = bef; stot[sub][o] = tot;
    __syncthreads();

    float2 T = make_float2(
        stot[0][o].x + stot[1][o].x + stot[2][o].x + stot[3][o].x,
        stot[0][o].y + stot[1][o].y + stot[2][o].y + stot[3][o].y);
    float2 p = make_float2(
        sbef[0][o].x + sbef[1][o].x + sbef[2][o].x + sbef[3][o].x,
        sbef[0][o].y + sbef[1][o].y + sbef[2][o].y + sbef[3][o].y);
    #pragma unroll
    for (int s2 = 0; s2 < 3; s2++)
        if (s2 < sub) { p.x += sloc[s2][o].x; p.y += sloc[s2][o].y; }

    // in-segment exclusive prefixes (33 rows) in smem
    __shared__ float2 sprefix[SROWS+1][64];
    #pragma unroll
    for (int rr = 0; rr < 8; rr++) {
        sprefix[sub*8 + rr][o] = p;
        p.x += e[rr].x * w[rr];
        p.y += e[rr].y * w[rr];
    }
    if (sub == 3) sprefix[SROWS][o] = p;
    __syncthreads();

    // finish all nodes bucketed in this segment, in chunks of 64
    __shared__ int    swd[64];
    __shared__ float2 sr[64];
    int start = g_bstart[b*(SEGS+1) + seg];
    int end   = g_bstart[b*(SEGS+1) + seg + 1];
    for (int c = start; c < end; c += 64) {
        int cnt = min(64, end - c);
        if (t < cnt) {
            int wd = g_bucket[b*NN + c + t];
            swd[t] = wd;
            sr[t]  = g_R12[b*NN + (wd & 2047)];
        }
        __syncthreads();
        for (int q = sub; q < cnt; q += 4) {
            int word = swd[q];
            int n = word & 2047;
            int j = (word >> 11) - seg*SROWS;   // 0..32
            float2 r = sr[q];
            float2 P = sprefix[j][o];
            float hp = r.x*(T.x - P.x) + r.y*P.y;
            out[(b*NN + n)*64 + o] = hp > 0.f ? hp : expm1f(hp);
        }
        __syncthreads();
    }
}

// ============================================================
extern "C" void kernel_launch(void* const* d_in, const int* in_sizes, int n_in,
                              void* d_out, int out_size)
{
    const float* h = (const float*)d_in[0];   // (8,2048,64)
    const float* W = (const float*)d_in[1];   // (64,64)
    const float* a = (const float*)d_in[2];   // (128,1)
    float* out = (float*)d_out;               // (8,2048,64)

    k1_gemm <<<NNODES/32, 256>>>(h, W, a);
    k2_sort <<<NB, 1024>>>();
    k3_fused<<<NBLK3, 256>>>(out);
}

// round 15
// speedup vs baseline: 1.0790x; 1.0790x over previous
#include <cuda_runtime.h>
#include <cuda_bf16.h>
#include <math.h>

// GAT layer, B=8, N=2048, F=64, ALPHA=0.2
// exp(lrelu(s+d)) = (d > -s) ? exp(s)*exp(d) : exp(.2s)*exp(.2d)
// => sort by d; fused segment-sum + prefix + apply kernel with one
//    grid-wide barrier; per-node denominators precomputed in k2.

#define NB 8
#define NN 2048
#define NF 64
#define NNODES (NB*NN)          // 16384
#define NR1 (NN+1)              // 2049
#define SEGS 64                 // segments per batch
#define SROWS 32                // rows per segment
#define NBLK3 (NB*SEGS)         // 512

// ---- device scratch (no allocation allowed) ----
__device__ float  g_Wh  [NNODES*NF];   // Wh rows, original order
__device__ float  g_s   [NNODES];      // s_src
__device__ float2 g_F12 [NNODES];      // {exp(s), exp(.2s)}
__device__ float  g_d   [NNODES];      // s_dst
__device__ float2 g_E12 [NNODES];      // {exp(d), exp(.2d)} original order
__device__ float2 g_E12s[NNODES];      // sorted order
__device__ int    g_perm[NNODES];      // sorted-rank -> local node idx
__device__ float2 g_R12 [NNODES];      // {f1/denom, f2/denom} per node
__device__ float2 g_seg12[NB*SEGS*NF]; // per-segment sums of E*Wh
__device__ int    g_bucket[NNODES];    // packed (k<<11)|node_local
__device__ int    g_bstart[NB*(SEGS+1)];
__device__ volatile int g_cnt;         // grid barrier counter (reset in k2)

// ============================================================
// K1: Wh = h@W ; s_src/s_dst + exps. 32 nodes/block, grid 512,
// 128 threads = 16 lanes x 8 groups, 4 nodes x 4 outs per thread.
// f-loop steps by 4 with float4 loads of BOTH W and h: 8 LDS.128
// feed 64 FFMA per step (LDS-rate was the k1 limiter).
// ============================================================
__global__ void __launch_bounds__(128) k1_gemm(
    const float* __restrict__ h, const float* __restrict__ W,
    const float* __restrict__ a)
{
    __shared__ float sW[64*64];
    __shared__ float4 sh4[32][16];
    __shared__ float sa[128];
    int tid = threadIdx.x;
    #pragma unroll
    for (int i = tid; i < 4096; i += 128) sW[i] = W[i];
    sa[tid] = a[tid];

    int base = blockIdx.x * 32;
    #pragma unroll
    for (int i = tid; i < 512; i += 128) {      // 32 rows x 16 float4
        int row = i >> 4, c4 = i & 15;
        sh4[row][c4] = *(const float4*)(h + (base + row)*64 + c4*4);
    }
    __syncthreads();

    int l = tid & 15, grp = tid >> 4;           // 16 lanes x 8 groups
    int o = l * 4;
    int nb = grp * 4;
    float4 acc[4] = {};
    #pragma unroll
    for (int f4 = 0; f4 < 16; f4++) {
        float4 w0 = *(const float4*)(&sW[(4*f4+0)*64 + o]);
        float4 w1 = *(const float4*)(&sW[(4*f4+1)*64 + o]);
        float4 w2 = *(const float4*)(&sW[(4*f4+2)*64 + o]);
        float4 w3 = *(const float4*)(&sW[(4*f4+3)*64 + o]);
        #pragma unroll
        for (int e = 0; e < 4; e++) {
            float4 hv = sh4[nb + e][f4];
            acc[e].x += hv.x*w0.x + hv.y*w1.x + hv.z*w2.x + hv.w*w3.x;
            acc[e].y += hv.x*w0.y + hv.y*w1.y + hv.z*w2.y + hv.w*w3.y;
            acc[e].z += hv.x*w0.z + hv.y*w1.z + hv.z*w2.z + hv.w*w3.z;
            acc[e].w += hv.x*w0.w + hv.y*w1.w + hv.z*w2.w + hv.w*w3.w;
        }
    }

    #pragma unroll
    for (int e = 0; e < 4; e++) {
        int node = base + nb + e;
        *(float4*)(&g_Wh[node*64 + o]) = acc[e];
        float ps = acc[e].x*sa[o]    + acc[e].y*sa[o+1]
                 + acc[e].z*sa[o+2]  + acc[e].w*sa[o+3];
        float pd = acc[e].x*sa[64+o] + acc[e].y*sa[64+o+1]
                 + acc[e].z*sa[64+o+2]+ acc[e].w*sa[64+o+3];
        #pragma unroll
        for (int m = 8; m >= 1; m >>= 1) {
            ps += __shfl_xor_sync(0xffffffffu, ps, m);
            pd += __shfl_xor_sync(0xffffffffu, pd, m);
        }
        if (l == 0) {
            g_s[node] = ps;
            g_F12[node] = make_float2(expf(ps), expf(0.2f*ps));
            g_d[node] = pd;
            g_E12[node] = make_float2(expf(pd), expf(0.2f*pd));
        }
    }
}

// ============================================================
// K2: per-batch hybrid bitonic sort (smem j>=32, shfl j<=16)
// + rank search + scalar scans + bucketing + R12. block 1024, grid 8.
// ============================================================
__device__ __forceinline__ unsigned int f2key(float f) {
    unsigned int b = __float_as_uint(f);
    unsigned int m = (unsigned int)(-(int)(b >> 31)) | 0x80000000u;
    return b ^ m;
}

__device__ __forceinline__ unsigned long long ce_shfl(
    unsigned long long e, int i, int j, int k)
{
    unsigned long long pv = __shfl_xor_sync(0xffffffffu, e, j >> 1);
    bool takeMin = (((i & j) == 0) == ((i & k) == 0));
    unsigned long long mn = e < pv ? e : pv;
    unsigned long long mx = e < pv ? pv : e;
    return takeMin ? mn : mx;
}

__device__ __forceinline__ void block_scan_2048(
    const float* sc, float* sout, float* wsum)
{
    int t = threadIdx.x, lane = t & 31, w = t >> 5;
    float x0 = sc[2*t], x1 = sc[2*t+1];
    float v = x0 + x1;
    float s = v;
    #pragma unroll
    for (int d2 = 1; d2 < 32; d2 <<= 1) {
        float nn = __shfl_up_sync(0xffffffffu, s, d2);
        if (lane >= d2) s += nn;
    }
    if (lane == 31) wsum[w] = s;
    __syncthreads();
    if (t < 32) {
        float ws = wsum[t]; float ss = ws;
        #pragma unroll
        for (int d2 = 1; d2 < 32; d2 <<= 1) {
            float nn = __shfl_up_sync(0xffffffffu, ss, d2);
            if (t >= d2) ss += nn;
        }
        wsum[t] = ss - ws;
    }
    __syncthreads();
    float incl = wsum[w] + s;
    float excl = incl - v;
    sout[2*t]   = excl;
    sout[2*t+1] = excl + x0;
    if (t == 1023) sout[2048] = incl;
}

__global__ void __launch_bounds__(1024) k2_sort(void)
{
    __shared__ unsigned long long skv[2048];
    __shared__ float sC1[NR1];
    __shared__ float sC2[NR1];
    __shared__ float wsum[32];
    __shared__ int hist[SEGS];
    __shared__ int hoff[SEGS];
    int b = blockIdx.x, t = threadIdx.x;
    int base = b * NN;
    int i0 = 2*t, i1 = 2*t + 1;

    if (b == 0 && t == 0) g_cnt = 0;   // reset grid barrier for k3
    if (t < SEGS) hist[t] = 0;
    {
        unsigned int ka = f2key(g_d[base + t]);
        unsigned int kb = f2key(g_d[base + t + 1024]);
        skv[t]      = ((unsigned long long)ka << 32) | (unsigned int)t;
        skv[t+1024] = ((unsigned long long)kb << 32) | (unsigned int)(t + 1024);
    }
    __syncthreads();

    // k = 2..32 entirely in registers
    {
        unsigned long long e0 = skv[i0], e1 = skv[i1];
        #pragma unroll
        for (int k = 2; k <= 32; k <<= 1) {
            #pragma unroll
            for (int j = k >> 1; j >= 2; j >>= 1) {
                e0 = ce_shfl(e0, i0, j, k);
                e1 = ce_shfl(e1, i1, j, k);
            }
            bool up = (i0 & k) == 0;
            unsigned long long mn = e0 < e1 ? e0 : e1;
            unsigned long long mx = e0 < e1 ? e1 : e0;
            e0 = up ? mn : mx;
            e1 = up ? mx : mn;
        }
        skv[i0] = e0; skv[i1] = e1;
    }
    __syncthreads();

    // k = 64..2048: strides >=32 in smem, <=16 in registers
    for (int k = 64; k <= 2048; k <<= 1) {
        for (int j = k >> 1; j >= 32; j >>= 1) {
            #pragma unroll
            for (int e = 0; e < 2; e++) {
                int i = t + e*1024;
                int ixj = i ^ j;
                if (ixj > i) {
                    bool up2 = ((i & k) == 0);
                    unsigned long long vi = skv[i], vj = skv[ixj];
                    if ((vi > vj) == up2) { skv[i] = vj; skv[ixj] = vi; }
                }
            }
            __syncthreads();
        }
        unsigned long long e0 = skv[i0], e1 = skv[i1];
        #pragma unroll
        for (int j = 16; j >= 2; j >>= 1) {
            e0 = ce_shfl(e0, i0, j, k);
            e1 = ce_shfl(e1, i1, j, k);
        }
        bool up = (i0 & k) == 0;
        unsigned long long mn = e0 < e1 ? e0 : e1;
        unsigned long long mx = e0 < e1 ? e1 : e0;
        skv[i0] = up ? mn : mx;
        skv[i1] = up ? mx : mn;
        __syncthreads();
    }

    // write perm + gathered exps
    int p0 = (int)(unsigned int)skv[t];
    int p1 = (int)(unsigned int)skv[t + 1024];
    g_perm[base + t]        = p0;
    g_perm[base + t + 1024] = p1;
    float2 ea = g_E12[base + p0];
    float2 eb = g_E12[base + p1];
    g_E12s[base + t]        = ea;
    g_E12s[base + t + 1024] = eb;

    // per-node rank search + bucket tally
    int kk[2], sg[2];
    #pragma unroll
    for (int e = 0; e < 2; e++) {
        int n = base + t + e*1024;
        unsigned int thrk = f2key(-g_s[n]);
        int lo = 0, hi = NN;
        while (lo < hi) {
            int mid = (lo + hi) >> 1;
            if ((unsigned int)(skv[mid] >> 32) <= thrk) lo = mid + 1; else hi = mid;
        }
        kk[e] = lo;
        sg[e] = min(lo >> 5, SEGS-1);
        atomicAdd(&hist[sg[e]], 1);
    }
    __syncthreads();

    if (t == 0) {
        int acc = 0;
        #pragma unroll
        for (int s2 = 0; s2 < SEGS; s2++) { hoff[s2] = acc; acc += hist[s2]; }
    }
    __syncthreads();
    if (t < SEGS) g_bstart[b*(SEGS+1) + t] = hoff[t];
    if (t == 0)   g_bstart[b*(SEGS+1) + SEGS] = NN;
    __syncthreads();

    #pragma unroll
    for (int e = 0; e < 2; e++) {
        int nloc = t + e*1024;
        int slot = atomicAdd(&hoff[sg[e]], 1);
        g_bucket[base + slot] = (kk[e] << 11) | nloc;
    }
    __syncthreads();

    // scalar prefix scans into smem (reuse skv as float buffer)
    float* sc = (float*)skv;
    sc[t] = ea.x; sc[t+1024] = eb.x;
    __syncthreads();
    block_scan_2048(sc, sC1, wsum);
    __syncthreads();
    sc[t] = ea.y; sc[t+1024] = eb.y;
    __syncthreads();
    block_scan_2048(sc, sC2, wsum);
    __syncthreads();

    // per-node reciprocal denominators
    float C1tot = sC1[NN];
    #pragma unroll
    for (int e = 0; e < 2; e++) {
        int n = base + t + e*1024;
        int k = kk[e];
        float2 f = g_F12[n];
        float denom = f.x*(C1tot - sC1[k]) + f.y*sC2[k];
        float inv = 1.0f / denom;
        g_R12[n] = make_float2(f.x*inv, f.y*inv);
    }
}

// ============================================================
// K3: fused segment sums + grid barrier + prefixes + apply.
// grid NBLK3=512, block 512 (o=tid&63, sub=tid>>6: 8 subs x 4 rows).
// 512 thr x 4 blocks/SM co-resident (592 slots >= 512 blocks).
// ============================================================
__global__ void __launch_bounds__(512, 4) k3_fused(float* __restrict__ out)
{
    int blk = blockIdx.x;
    int b = blk >> 6, seg = blk & 63;
    int t = threadIdx.x;
    int o = t & 63, sub = t >> 6;

    __shared__ int    sperm[SROWS];
    __shared__ float2 sE[SROWS];
    if (t < SROWS) {
        sperm[t] = g_perm[b*NN + seg*SROWS + t];
        sE[t]    = g_E12s[b*NN + seg*SROWS + t];
    }
    __syncthreads();

    // own 4-row partials; cache gathered Wh + E in registers
    float w[4]; float2 e[4];
    float2 loc = make_float2(0.f, 0.f);
    #pragma unroll
    for (int rr = 0; rr < 4; rr++) {
        int lr = sub*4 + rr;
        w[rr] = g_Wh[(b*NN + sperm[lr])*64 + o];
        e[rr] = sE[lr];
        loc.x += e[rr].x * w[rr];
        loc.y += e[rr].y * w[rr];
    }

    __shared__ float2 sloc[8][64];
    sloc[sub][o] = loc;
    __syncthreads();

    // publish this segment's aggregate
    if (sub == 0) {
        float2 agg = make_float2(0.f, 0.f);
        #pragma unroll
        for (int s2 = 0; s2 < 8; s2++) { agg.x += sloc[s2][o].x; agg.y += sloc[s2][o].y; }
        g_seg12[blk*64 + o] = agg;
    }
    __syncthreads();

    // grid-wide barrier: release(writes) -> arrive -> spin
    if (t == 0) {
        __threadfence();
        atomicAdd((int*)&g_cnt, 1);
        while (g_cnt < NBLK3) { }
    }
    __syncthreads();

    // strided pass over all 64 segment sums
    float2 bef = make_float2(0.f, 0.f);
    float2 tot = make_float2(0.f, 0.f);
    for (int s = sub; s < SEGS; s += 8) {
        float2 v = __ldcg(&g_seg12[(b*SEGS + s)*64 + o]);
        tot.x += v.x; tot.y += v.y;
        if (s < seg) { bef.x += v.x; bef.y += v.y; }
    }

    __shared__ float2 sbef[8][64], stot[8][64];
    sbef[sub][o] = bef; stot[sub][o] = tot;
    __syncthreads();

    float2 T = make_float2(0.f, 0.f);
    float2 p = make_float2(0.f, 0.f);
    #pragma unroll
    for (int s2 = 0; s2 < 8; s2++) {
        T.x += stot[s2][o].x; T.y += stot[s2][o].y;
        p.x += sbef[s2][o].x; p.y += sbef[s2][o].y;
    }
    #pragma unroll
    for (int s2 = 0; s2 < 7; s2++)
        if (s2 < sub) { p.x += sloc[s2][o].x; p.y += sloc[s2][o].y; }

    // in-segment exclusive prefixes (33 rows) in smem
    __shared__ float2 sprefix[SROWS+1][64];
    #pragma unroll
    for (int rr = 0; rr < 4; rr++) {
        sprefix[sub*4 + rr][o] = p;
        p.x += e[rr].x * w[rr];
        p.y += e[rr].y * w[rr];
    }
    if (sub == 7) sprefix[SROWS][o] = p;
    __syncthreads();

    // finish all nodes bucketed in this segment, in chunks of 128
    __shared__ int    swd[128];
    __shared__ float2 sr[128];
    int start = g_bstart[b*(SEGS+1) + seg];
    int end   = g_bstart[b*(SEGS+1) + seg + 1];
    for (int c = start; c < end; c += 128) {
        int cnt = min(128, end - c);
        if (t < cnt) {
            int wd = g_bucket[b*NN + c + t];
            swd[t] = wd;
            sr[t]  = g_R12[b*NN + (wd & 2047)];
        }
        __syncthreads();
        for (int q = sub; q < cnt; q += 8) {
            int word = swd[q];
            int n = word & 2047;
            int j = (word >> 11) - seg*SROWS;   // 0..32
            float2 r = sr[q];
            float2 P = sprefix[j][o];
            float hp = r.x*(T.x - P.x) + r.y*P.y;
            out[(b*NN + n)*64 + o] = hp > 0.f ? hp : expm1f(hp);
        }
        __syncthreads();
    }
}

// ============================================================
extern "C" void kernel_launch(void* const* d_in, const int* in_sizes, int n_in,
                              void* d_out, int out_size)
{
    const float* h = (const float*)d_in[0];   // (8,2048,64)
    const float* W = (const float*)d_in[1];   // (64,64)
    const float* a = (const float*)d_in[2];   // (128,1)
    float* out = (float*)d_out;               // (8,2048,64)

    k1_gemm <<<NNODES/32, 128>>>(h, W, a);
    k2_sort <<<NB, 1024>>>();
    k3_fused<<<NBLK3, 512>>>(out);
}